// round 3
// baseline (speedup 1.0000x reference)
#include <cuda_runtime.h>

#define BATCH 2
#define LSEQ 2048
#define HDIM 1024
#define NST 16
#define MROWS (BATCH*LSEQ)     // 4096
#define DT_MIN_V 0.001f
#define DT_MAX_V 0.02f
#define NCHUNK 32
#define CHLEN (LSEQ/NCHUNK)    // 64
#define NCH (BATCH*HDIM)       // 2048
#define TL 16
#define LOG2E 1.4426950408889634f

// Scratch (__device__ globals: allocation-free rule)
__device__ float g_dtT[BATCH*HDIM*LSEQ];       // (B,H,L)
__device__ float g_P  [NCHUNK*NCH*NST];        // per-chunk prod(abar)
__device__ float g_S  [NCHUNK*NCH*NST];        // per-chunk local end state (x' units)
__device__ float g_Xin[NCHUNK*NCH*NST];        // per-chunk initial state (x' units)

typedef unsigned long long u64;

__device__ __forceinline__ u64 ffma2(u64 a, u64 b, u64 c){
    u64 d;
    asm("fma.rn.f32x2 %0, %1, %2, %3;" : "=l"(d) : "l"(a), "l"(b), "l"(c));
    return d;
}
__device__ __forceinline__ u64 f2u(float x, float y){
    u64 v; asm("mov.b64 %0, {%1, %2};" : "=l"(v) : "f"(x), "f"(y)); return v;
}
__device__ __forceinline__ float2 u2f(u64 v){
    float2 r; asm("mov.b64 {%0, %1}, %2;" : "=f"(r.x), "=f"(r.y) : "l"(v)); return r;
}

// ---------------------------------------------------------------------------
// TF32 tensor-core GEMM (unchanged from R2): log_dt = U·Wᵀ + b; dt=clamp(exp)
// writes g_dtT[(b,g,l)] (fused transpose).
// ---------------------------------------------------------------------------
__device__ __forceinline__ void cp16(float* s, const float* g){
    unsigned sa = (unsigned)__cvta_generic_to_shared(s);
    asm volatile("cp.async.cg.shared.global [%0], [%1], 16;" :: "r"(sa), "l"(g));
}
__device__ __forceinline__ void ldsm4(unsigned* r, unsigned addr){
    asm volatile("ldmatrix.sync.aligned.m8n8.x4.shared.b16 {%0,%1,%2,%3}, [%4];"
        : "=r"(r[0]), "=r"(r[1]), "=r"(r[2]), "=r"(r[3]) : "r"(addr));
}
__device__ __forceinline__ void mma_tf32(float* d, const unsigned* a,
                                         unsigned b0, unsigned b1){
    asm volatile(
        "mma.sync.aligned.m16n8k8.row.col.f32.tf32.tf32.f32 "
        "{%0,%1,%2,%3}, {%4,%5,%6,%7}, {%8,%9}, {%0,%1,%2,%3};"
        : "+f"(d[0]), "+f"(d[1]), "+f"(d[2]), "+f"(d[3])
        : "r"(a[0]), "r"(a[1]), "r"(a[2]), "r"(a[3]), "r"(b0), "r"(b1));
}

__global__ __launch_bounds__(256) void gemm_tf32_kernel(
        const float* __restrict__ U, const float* __restrict__ W,
        const float* __restrict__ bias){
    extern __shared__ float smem[];
    const int tid  = threadIdx.x;
    const int lane = tid & 31;
    const int wid  = tid >> 5;
    const int wm   = wid & 1;
    const int wn   = wid >> 1;
    const int bm   = blockIdx.y * 128;
    const int bn   = blockIdx.x * 128;

    float acc[4][4][4];
    #pragma unroll
    for (int i = 0; i < 4; i++)
        #pragma unroll
        for (int j = 0; j < 4; j++)
            #pragma unroll
            for (int r = 0; r < 4; r++) acc[i][j][r] = 0.f;

    const int lrow = tid >> 3;
    const int lkc  = tid & 7;

    unsigned smemBase = (unsigned)__cvta_generic_to_shared(smem);
    const unsigned aRowOff = (unsigned)((wm * 64 + (lane & 15)) * 128);
    const unsigned bRowOff = (unsigned)((wn * 32 + ((lane & 16) >> 1) + (lane & 7)) * 128);
    int physA[4], physB[4];
    #pragma unroll
    for (int ks = 0; ks < 4; ks++){
        physA[ks] = ((2 * ks + (lane >> 4)) ^ (lane & 7)) * 16;
        physB[ks] = ((2 * ks + ((lane >> 3) & 1)) ^ (lane & 7)) * 16;
    }

    #define LOAD_TILE(KT, STG) do {                                            \
        float* A_s = smem + (STG) * 8192;                                      \
        float* B_s = A_s + 4096;                                               \
        _Pragma("unroll")                                                      \
        for (int i = 0; i < 4; i++){                                           \
            int row  = lrow + i * 32;                                          \
            int phys = lkc ^ (row & 7);                                        \
            cp16(A_s + row * 32 + phys * 4,                                    \
                 U + (size_t)(bm + row) * 1024 + (KT) * 32 + lkc * 4);         \
            cp16(B_s + row * 32 + phys * 4,                                    \
                 W + (size_t)(bn + row) * 1024 + (KT) * 32 + lkc * 4);         \
        }                                                                      \
        asm volatile("cp.async.commit_group;");                                \
    } while (0)

    LOAD_TILE(0, 0);

    for (int kt = 0; kt < 32; kt++){
        const int cur = kt & 1;
        if (kt < 31) LOAD_TILE(kt + 1, cur ^ 1);
        if (kt < 31) asm volatile("cp.async.wait_group 1;");
        else         asm volatile("cp.async.wait_group 0;");
        __syncthreads();

        unsigned aB = smemBase + cur * 32768 + aRowOff;
        unsigned bB = smemBase + cur * 32768 + 16384 + bRowOff;
        #pragma unroll
        for (int ks = 0; ks < 4; ks++){
            unsigned a[4][4], bb[2][4];
            #pragma unroll
            for (int mt = 0; mt < 4; mt++)
                ldsm4(a[mt], aB + mt * 16 * 128 + physA[ks]);
            #pragma unroll
            for (int tp = 0; tp < 2; tp++)
                ldsm4(bb[tp], bB + tp * 16 * 128 + physB[ks]);
            #pragma unroll
            for (int mt = 0; mt < 4; mt++)
                #pragma unroll
                for (int nt = 0; nt < 4; nt++)
                    mma_tf32(acc[mt][nt], a[mt],
                             bb[nt >> 1][(nt & 1) * 2], bb[nt >> 1][(nt & 1) * 2 + 1]);
        }
        __syncthreads();
    }

    const int rbase = bm + wm * 64 + (lane >> 2);
    const int gbase = bn + wn * 32 + 2 * (lane & 3);
    float bv[4][2];
    #pragma unroll
    for (int nt = 0; nt < 4; nt++){
        bv[nt][0] = __ldg(bias + gbase + nt * 8);
        bv[nt][1] = __ldg(bias + gbase + nt * 8 + 1);
    }
    #pragma unroll
    for (int mt = 0; mt < 4; mt++)
        #pragma unroll
        for (int nt = 0; nt < 4; nt++)
            #pragma unroll
            for (int r = 0; r < 4; r++){
                const int m = rbase + mt * 16 + ((r >= 2) ? 8 : 0);
                const int g = gbase + nt * 8 + (r & 1);
                float v = acc[mt][nt][r] + bv[nt][r & 1];
                v = __expf(v);
                v = fminf(fmaxf(v, DT_MIN_V), DT_MAX_V);
                const int b = m >> 11, l = m & 2047;
                g_dtT[((size_t)b * HDIM + g) * LSEQ + l] = v;
            }
}

// ---------------------------------------------------------------------------
// Rare-path helper: one unclipped dt step for one thread (scalar, 16 states).
//   x'_n = x'_n * abar_n + ((abar_n-1)/(am_n-1)) * u
// ---------------------------------------------------------------------------
__device__ __noinline__ void slow_step(u64* x2, const u64* am2,
                                       const float* __restrict__ Alog,
                                       int h, float dtv, float uu){
    #pragma unroll
    for (int i = 0; i < 8; i++){
        float2 xv = u2f(x2[i]);
        float2 av = u2f(am2[i]);
        #pragma unroll
        for (int p = 0; p < 2; p++){
            const int n = 2 * i + p;
            const float A = -expf(__ldg(Alog + h * NST + n));
            const float abar = exp2f(dtv * A * LOG2E);
            const float amn = p ? av.y : av.x;
            const float bu = (abar - 1.f) / (amn - 1.f) * uu;
            float xn = p ? xv.y : xv.x;
            xn = fmaf(xn, abar, bu);
            if (p) xv.y = xn; else xv.x = xn;
        }
        x2[i] = f2u(xv.x, xv.y);
    }
}

// ---------------------------------------------------------------------------
// Pass 1: per-(channel,chunk) reduce. Thread = one channel-chunk, 16 states
// in f32x2 regs. dt: per-thread float4 from dtT. u: smem-staged from (B,L,H).
// Outputs P_n = exp2(A_n*log2e*Σdt), S_n = local end state (x' units).
// ---------------------------------------------------------------------------
__global__ __launch_bounds__(128) void scan_reduce_kernel(
        const float* __restrict__ Alog, const float* __restrict__ u){
    __shared__ float us[TL][128];
    const int tid = threadIdx.x;
    const int sbase = blockIdx.x * 128;
    const int s = sbase + tid;                 // channel 0..2047
    const int chunk = blockIdx.y;
    const int b = s >> 10;
    const int h = s & 1023;
    const int h0 = sbase & 1023;

    u64 am2[8], x2[8];
    #pragma unroll
    for (int i = 0; i < 8; i++){
        const float A0 = -expf(__ldg(Alog + h * NST + 2 * i));
        const float A1 = -expf(__ldg(Alog + h * NST + 2 * i + 1));
        am2[i] = f2u(exp2f(0.02f * A0 * LOG2E), exp2f(0.02f * A1 * LOG2E));
        x2[i] = 0ull;
    }
    float dtsum = 0.f;

    const float* dtp = g_dtT + (size_t)(b * HDIM + h) * LSEQ + chunk * CHLEN;
    const float* ubase = u + (size_t)b * LSEQ * HDIM + h0;

    for (int t4 = 0; t4 < CHLEN / TL; t4++){
        const int l0 = chunk * CHLEN + t4 * TL;
        __syncthreads();
        #pragma unroll
        for (int p = 0; p < 4; p++){
            const int row = p * 4 + (tid >> 5);
            *(float4*)&us[row][(tid & 31) * 4] =
                *(const float4*)&ubase[(size_t)(l0 + row) * HDIM + (tid & 31) * 4];
        }
        __syncthreads();
        #pragma unroll
        for (int q = 0; q < 4; q++){
            const float4 dq = *(const float4*)(dtp + t4 * TL + q * 4);
            #pragma unroll
            for (int j = 0; j < 4; j++){
                const float dtv = (j == 0) ? dq.x : (j == 1) ? dq.y : (j == 2) ? dq.z : dq.w;
                const float uu = us[q * 4 + j][tid];
                dtsum += dtv;
                if (dtv == DT_MAX_V){
                    const u64 u2 = f2u(uu, uu);
                    #pragma unroll
                    for (int i = 0; i < 8; i++)
                        x2[i] = ffma2(x2[i], am2[i], u2);
                } else {
                    slow_step(x2, am2, Alog, h, dtv, uu);
                }
            }
        }
    }

    // write P and S (16 consecutive floats each -> coalesced across threads)
    float* Pp = g_P + ((size_t)chunk * NCH + s) * NST;
    float* Sp = g_S + ((size_t)chunk * NCH + s) * NST;
    #pragma unroll
    for (int i = 0; i < 8; i++){
        const float A0 = -expf(__ldg(Alog + h * NST + 2 * i));
        const float A1 = -expf(__ldg(Alog + h * NST + 2 * i + 1));
        const float2 xv = u2f(x2[i]);
        Pp[2 * i]     = exp2f(A0 * LOG2E * dtsum);
        Pp[2 * i + 1] = exp2f(A1 * LOG2E * dtsum);
        Sp[2 * i]     = xv.x;
        Sp[2 * i + 1] = xv.y;
    }
}

// ---------------------------------------------------------------------------
// Pass 2: stitch boundary states. Thread = (channel, n-quad). Loads batched
// 8 chunks deep for MLP; 4 groups of (8 prefetch + 8 sequential folds).
// ---------------------------------------------------------------------------
__global__ void scan_stitch_kernel(){
    const int id = blockIdx.x * blockDim.x + threadIdx.x;  // 0..8191
    const float4* P4 = (const float4*)g_P;
    const float4* S4 = (const float4*)g_S;
    float4* X4 = (float4*)g_Xin;
    const int stride = NCH * NST / 4;                      // 8192 float4 per chunk
    float4 x = make_float4(0.f, 0.f, 0.f, 0.f);
    #pragma unroll
    for (int g = 0; g < 4; g++){
        float4 Pg[8], Sg[8];
        #pragma unroll
        for (int c = 0; c < 8; c++){
            Pg[c] = P4[(size_t)(g * 8 + c) * stride + id];
            Sg[c] = S4[(size_t)(g * 8 + c) * stride + id];
        }
        #pragma unroll
        for (int c = 0; c < 8; c++){
            X4[(size_t)(g * 8 + c) * stride + id] = x;
            x.x = fmaf(Pg[c].x, x.x, Sg[c].x);
            x.y = fmaf(Pg[c].y, x.y, Sg[c].y);
            x.z = fmaf(Pg[c].z, x.z, Sg[c].z);
            x.w = fmaf(Pg[c].w, x.w, Sg[c].w);
        }
    }
}

// ---------------------------------------------------------------------------
// Pass 3: final scan + output. Thread = one channel-chunk. y = Σ C'_n x'_n
// + D·u with C'_n = C_n*(am_n-1)*B_n/A_n. Coalesced out stores (128 h/block).
// ---------------------------------------------------------------------------
__global__ __launch_bounds__(128) void scan_final_kernel(
        const float* __restrict__ Alog, const float* __restrict__ Bp,
        const float* __restrict__ Cp, const float* __restrict__ Dp,
        const float* __restrict__ u, float* __restrict__ out){
    __shared__ float us[TL][128];
    const int tid = threadIdx.x;
    const int sbase = blockIdx.x * 128;
    const int s = sbase + tid;
    const int chunk = blockIdx.y;
    const int b = s >> 10;
    const int h = s & 1023;
    const int h0 = sbase & 1023;

    u64 am2[8], c2[8], x2[8];
    #pragma unroll
    for (int i = 0; i < 8; i++){
        const float A0 = -expf(__ldg(Alog + h * NST + 2 * i));
        const float A1 = -expf(__ldg(Alog + h * NST + 2 * i + 1));
        const float am0 = exp2f(0.02f * A0 * LOG2E);
        const float am1 = exp2f(0.02f * A1 * LOG2E);
        am2[i] = f2u(am0, am1);
        const float s0 = (am0 - 1.f) * __ldg(Bp + h * NST + 2 * i) / A0;
        const float s1 = (am1 - 1.f) * __ldg(Bp + h * NST + 2 * i + 1) / A1;
        c2[i] = f2u(__ldg(Cp + h * NST + 2 * i) * s0,
                    __ldg(Cp + h * NST + 2 * i + 1) * s1);
    }
    const float Dh = __ldg(Dp + h);

    {   // initial state
        const float4* Xq = (const float4*)(g_Xin + ((size_t)chunk * NCH + s) * NST);
        #pragma unroll
        for (int i = 0; i < 4; i++){
            const float4 v = Xq[i];
            x2[2 * i]     = f2u(v.x, v.y);
            x2[2 * i + 1] = f2u(v.z, v.w);
        }
    }

    const float* dtp = g_dtT + (size_t)(b * HDIM + h) * LSEQ + chunk * CHLEN;
    const float* ubase = u + (size_t)b * LSEQ * HDIM + h0;
    float* obase = out + (size_t)b * LSEQ * HDIM + h0 + tid;

    for (int t4 = 0; t4 < CHLEN / TL; t4++){
        const int l0 = chunk * CHLEN + t4 * TL;
        __syncthreads();
        #pragma unroll
        for (int p = 0; p < 4; p++){
            const int row = p * 4 + (tid >> 5);
            *(float4*)&us[row][(tid & 31) * 4] =
                *(const float4*)&ubase[(size_t)(l0 + row) * HDIM + (tid & 31) * 4];
        }
        __syncthreads();
        #pragma unroll
        for (int q = 0; q < 4; q++){
            const float4 dq = *(const float4*)(dtp + t4 * TL + q * 4);
            #pragma unroll
            for (int j = 0; j < 4; j++){
                const float dtv = (j == 0) ? dq.x : (j == 1) ? dq.y : (j == 2) ? dq.z : dq.w;
                const float uu = us[q * 4 + j][tid];
                if (dtv == DT_MAX_V){
                    const u64 u2 = f2u(uu, uu);
                    #pragma unroll
                    for (int i = 0; i < 8; i++)
                        x2[i] = ffma2(x2[i], am2[i], u2);
                } else {
                    slow_step(x2, am2, Alog, h, dtv, uu);
                }
                u64 y2 = 0ull;
                #pragma unroll
                for (int i = 0; i < 8; i++)
                    y2 = ffma2(c2[i], x2[i], y2);
                const float2 yv = u2f(y2);
                obase[(size_t)(l0 + q * 4 + j) * HDIM] = fmaf(Dh, uu, yv.x + yv.y);
            }
        }
    }
}

// ---------------------------------------------------------------------------
extern "C" void kernel_launch(void* const* d_in, const int* in_sizes, int n_in,
                              void* d_out, int out_size){
    const float* u    = (const float*)d_in[0];
    const float* Alog = (const float*)d_in[1];
    const float* Bp   = (const float*)d_in[2];
    const float* Cp   = (const float*)d_in[3];
    const float* Dp   = (const float*)d_in[4];
    const float* Wdt  = (const float*)d_in[5];
    const float* bdt  = (const float*)d_in[6];
    float* out = (float*)d_out;

    cudaFuncSetAttribute(gemm_tf32_kernel,
                         cudaFuncAttributeMaxDynamicSharedMemorySize, 65536);

    dim3 ggrid(HDIM / 128, MROWS / 128);            // (8, 32)
    gemm_tf32_kernel<<<ggrid, 256, 65536>>>(u, Wdt, bdt);

    scan_reduce_kernel<<<dim3(NCH / 128, NCHUNK), 128>>>(Alog, u);
    scan_stitch_kernel<<<NCH * NST / 4 / 256, 256>>>();
    scan_final_kernel<<<dim3(NCH / 128, NCHUNK), 128>>>(Alog, Bp, Cp, Dp, u, out);
}

// round 4
// speedup vs baseline: 1.0301x; 1.0301x over previous
#include <cuda_runtime.h>

#define BATCH 2
#define LSEQ 2048
#define HDIM 1024
#define NST 16
#define MROWS (BATCH*LSEQ)     // 4096
#define DT_MIN_V 0.001f
#define DT_MAX_V 0.02f
#define NCHUNK 64
#define CHLEN (LSEQ/NCHUNK)    // 32
#define NCH (BATCH*HDIM)       // 2048
#define LOG2E 1.4426950408889634f

// Scratch (__device__ globals: allocation-free rule)
__device__ float g_dt [BATCH*LSEQ*HDIM];       // (B,L,H) — natural layout
__device__ float g_P  [NCHUNK*NCH*NST];        // per-chunk prod(abar)
__device__ float g_S  [NCHUNK*NCH*NST];        // per-chunk local end state (x' units)
__device__ float g_Xin[NCHUNK*NCH*NST];        // per-chunk initial state (x' units)

typedef unsigned long long u64;

__device__ __forceinline__ u64 ffma2(u64 a, u64 b, u64 c){
    u64 d;
    asm("fma.rn.f32x2 %0, %1, %2, %3;" : "=l"(d) : "l"(a), "l"(b), "l"(c));
    return d;
}
__device__ __forceinline__ u64 f2u(float x, float y){
    u64 v; asm("mov.b64 %0, {%1, %2};" : "=l"(v) : "f"(x), "f"(y)); return v;
}
__device__ __forceinline__ float2 u2f(u64 v){
    float2 r; asm("mov.b64 {%0, %1}, %2;" : "=f"(r.x), "=f"(r.y) : "l"(v)); return r;
}

// ---------------------------------------------------------------------------
// TF32 tensor-core GEMM: log_dt = U·Wᵀ + b; dt = clamp(exp(log_dt)).
// Writes g_dt in (B,L,H) layout (coalesced epilogue, no transpose anywhere).
// ---------------------------------------------------------------------------
__device__ __forceinline__ void cp16(float* s, const float* g){
    unsigned sa = (unsigned)__cvta_generic_to_shared(s);
    asm volatile("cp.async.cg.shared.global [%0], [%1], 16;" :: "r"(sa), "l"(g));
}
__device__ __forceinline__ void ldsm4(unsigned* r, unsigned addr){
    asm volatile("ldmatrix.sync.aligned.m8n8.x4.shared.b16 {%0,%1,%2,%3}, [%4];"
        : "=r"(r[0]), "=r"(r[1]), "=r"(r[2]), "=r"(r[3]) : "r"(addr));
}
__device__ __forceinline__ void mma_tf32(float* d, const unsigned* a,
                                         unsigned b0, unsigned b1){
    asm volatile(
        "mma.sync.aligned.m16n8k8.row.col.f32.tf32.tf32.f32 "
        "{%0,%1,%2,%3}, {%4,%5,%6,%7}, {%8,%9}, {%0,%1,%2,%3};"
        : "+f"(d[0]), "+f"(d[1]), "+f"(d[2]), "+f"(d[3])
        : "r"(a[0]), "r"(a[1]), "r"(a[2]), "r"(a[3]), "r"(b0), "r"(b1));
}

__global__ __launch_bounds__(256) void gemm_tf32_kernel(
        const float* __restrict__ U, const float* __restrict__ W,
        const float* __restrict__ bias){
    extern __shared__ float smem[];
    const int tid  = threadIdx.x;
    const int lane = tid & 31;
    const int wid  = tid >> 5;
    const int wm   = wid & 1;
    const int wn   = wid >> 1;
    const int bm   = blockIdx.y * 128;
    const int bn   = blockIdx.x * 128;

    float acc[4][4][4];
    #pragma unroll
    for (int i = 0; i < 4; i++)
        #pragma unroll
        for (int j = 0; j < 4; j++)
            #pragma unroll
            for (int r = 0; r < 4; r++) acc[i][j][r] = 0.f;

    const int lrow = tid >> 3;
    const int lkc  = tid & 7;

    unsigned smemBase = (unsigned)__cvta_generic_to_shared(smem);
    const unsigned aRowOff = (unsigned)((wm * 64 + (lane & 15)) * 128);
    const unsigned bRowOff = (unsigned)((wn * 32 + ((lane & 16) >> 1) + (lane & 7)) * 128);
    int physA[4], physB[4];
    #pragma unroll
    for (int ks = 0; ks < 4; ks++){
        physA[ks] = ((2 * ks + (lane >> 4)) ^ (lane & 7)) * 16;
        physB[ks] = ((2 * ks + ((lane >> 3) & 1)) ^ (lane & 7)) * 16;
    }

    #define LOAD_TILE(KT, STG) do {                                            \
        float* A_s = smem + (STG) * 8192;                                      \
        float* B_s = A_s + 4096;                                               \
        _Pragma("unroll")                                                      \
        for (int i = 0; i < 4; i++){                                           \
            int row  = lrow + i * 32;                                          \
            int phys = lkc ^ (row & 7);                                        \
            cp16(A_s + row * 32 + phys * 4,                                    \
                 U + (size_t)(bm + row) * 1024 + (KT) * 32 + lkc * 4);         \
            cp16(B_s + row * 32 + phys * 4,                                    \
                 W + (size_t)(bn + row) * 1024 + (KT) * 32 + lkc * 4);         \
        }                                                                      \
        asm volatile("cp.async.commit_group;");                                \
    } while (0)

    LOAD_TILE(0, 0);

    for (int kt = 0; kt < 32; kt++){
        const int cur = kt & 1;
        if (kt < 31) LOAD_TILE(kt + 1, cur ^ 1);
        if (kt < 31) asm volatile("cp.async.wait_group 1;");
        else         asm volatile("cp.async.wait_group 0;");
        __syncthreads();

        unsigned aB = smemBase + cur * 32768 + aRowOff;
        unsigned bB = smemBase + cur * 32768 + 16384 + bRowOff;
        #pragma unroll
        for (int ks = 0; ks < 4; ks++){
            unsigned a[4][4], bb[2][4];
            #pragma unroll
            for (int mt = 0; mt < 4; mt++)
                ldsm4(a[mt], aB + mt * 16 * 128 + physA[ks]);
            #pragma unroll
            for (int tp = 0; tp < 2; tp++)
                ldsm4(bb[tp], bB + tp * 16 * 128 + physB[ks]);
            #pragma unroll
            for (int mt = 0; mt < 4; mt++)
                #pragma unroll
                for (int nt = 0; nt < 4; nt++)
                    mma_tf32(acc[mt][nt], a[mt],
                             bb[nt >> 1][(nt & 1) * 2], bb[nt >> 1][(nt & 1) * 2 + 1]);
        }
        __syncthreads();
    }

    const int rbase = bm + wm * 64 + (lane >> 2);
    const int gbase = bn + wn * 32 + 2 * (lane & 3);
    float bv[4][2];
    #pragma unroll
    for (int nt = 0; nt < 4; nt++){
        bv[nt][0] = __ldg(bias + gbase + nt * 8);
        bv[nt][1] = __ldg(bias + gbase + nt * 8 + 1);
    }
    #pragma unroll
    for (int mt = 0; mt < 4; mt++)
        #pragma unroll
        for (int nt = 0; nt < 4; nt++)
            #pragma unroll
            for (int rr = 0; rr < 2; rr++){
                const int m = rbase + mt * 16 + rr * 8;
                float2 o;
                float v0 = acc[mt][nt][rr * 2]     + bv[nt][0];
                float v1 = acc[mt][nt][rr * 2 + 1] + bv[nt][1];
                o.x = fminf(fmaxf(__expf(v0), DT_MIN_V), DT_MAX_V);
                o.y = fminf(fmaxf(__expf(v1), DT_MIN_V), DT_MAX_V);
                *(float2*)&g_dt[(size_t)m * HDIM + gbase + nt * 8] = o;
            }
}

// ---------------------------------------------------------------------------
// Rare-path helper: one unclipped dt step (scalar over 16 states).
//   x'_n = x'_n * abar_n + ((abar_n-1)/(am_n-1)) * u
// ---------------------------------------------------------------------------
__device__ __noinline__ void slow_step(u64* x2, const u64* am2,
                                       const float* __restrict__ Alog,
                                       int h, float dtv, float uu){
    #pragma unroll
    for (int i = 0; i < 8; i++){
        float2 xv = u2f(x2[i]);
        float2 av = u2f(am2[i]);
        #pragma unroll
        for (int p = 0; p < 2; p++){
            const int n = 2 * i + p;
            const float A = -expf(__ldg(Alog + h * NST + n));
            const float abar = exp2f(dtv * A * LOG2E);
            const float amn = p ? av.y : av.x;
            const float bu = (abar - 1.f) / (amn - 1.f) * uu;
            float xn = p ? xv.y : xv.x;
            xn = fmaf(xn, abar, bu);
            if (p) xv.y = xn; else xv.x = xn;
        }
        x2[i] = f2u(xv.x, xv.y);
    }
}

// ---------------------------------------------------------------------------
// Pass 1: per-(channel,chunk) reduce. Thread = one channel-chunk; u and dt
// both read coalesced from (B,L,H) with identical indices.
// ---------------------------------------------------------------------------
__global__ __launch_bounds__(128) void scan_reduce_kernel(
        const float* __restrict__ Alog, const float* __restrict__ u){
    const int tid = threadIdx.x;
    const int s = blockIdx.x * 128 + tid;      // channel 0..2047
    const int chunk = blockIdx.y;
    const int b = s >> 10;
    const int h = s & 1023;

    u64 am2[8], x2[8];
    #pragma unroll
    for (int i = 0; i < 8; i++){
        const float A0 = -expf(__ldg(Alog + h * NST + 2 * i));
        const float A1 = -expf(__ldg(Alog + h * NST + 2 * i + 1));
        am2[i] = f2u(exp2f(0.02f * A0 * LOG2E), exp2f(0.02f * A1 * LOG2E));
        x2[i] = 0ull;
    }
    float dtsum = 0.f;

    const size_t base = ((size_t)(b * LSEQ + chunk * CHLEN)) * HDIM + h;
    const float* up = u + base;
    const float* dp = g_dt + base;

    #pragma unroll 2
    for (int t = 0; t < CHLEN; t += 4){
        float uu[4], dv[4];
        #pragma unroll
        for (int j = 0; j < 4; j++){
            uu[j] = __ldg(up + (size_t)(t + j) * HDIM);
            dv[j] = __ldg(dp + (size_t)(t + j) * HDIM);
        }
        #pragma unroll
        for (int j = 0; j < 4; j++){
            dtsum += dv[j];
            if (dv[j] == DT_MAX_V){
                const u64 u2v = f2u(uu[j], uu[j]);
                #pragma unroll
                for (int i = 0; i < 8; i++)
                    x2[i] = ffma2(x2[i], am2[i], u2v);
            } else {
                slow_step(x2, am2, Alog, h, dv[j], uu[j]);
            }
        }
    }

    float* Pp = g_P + ((size_t)chunk * NCH + s) * NST;
    float* Sp = g_S + ((size_t)chunk * NCH + s) * NST;
    #pragma unroll
    for (int i = 0; i < 8; i++){
        const float A0 = -expf(__ldg(Alog + h * NST + 2 * i));
        const float A1 = -expf(__ldg(Alog + h * NST + 2 * i + 1));
        const float2 xv = u2f(x2[i]);
        Pp[2 * i]     = exp2f(A0 * LOG2E * dtsum);
        Pp[2 * i + 1] = exp2f(A1 * LOG2E * dtsum);
        Sp[2 * i]     = xv.x;
        Sp[2 * i + 1] = xv.y;
    }
}

// ---------------------------------------------------------------------------
// Pass 2: stitch boundary states. Thread = (channel, n-quad); 8 groups of
// (8 batched loads + 8 sequential folds) over the 64 chunks.
// ---------------------------------------------------------------------------
__global__ void scan_stitch_kernel(){
    const int id = blockIdx.x * blockDim.x + threadIdx.x;  // 0..8191
    const float4* P4 = (const float4*)g_P;
    const float4* S4 = (const float4*)g_S;
    float4* X4 = (float4*)g_Xin;
    const int stride = NCH * NST / 4;                      // 8192 float4 per chunk
    float4 x = make_float4(0.f, 0.f, 0.f, 0.f);
    #pragma unroll
    for (int g = 0; g < 8; g++){
        float4 Pg[8], Sg[8];
        #pragma unroll
        for (int c = 0; c < 8; c++){
            Pg[c] = P4[(size_t)(g * 8 + c) * stride + id];
            Sg[c] = S4[(size_t)(g * 8 + c) * stride + id];
        }
        #pragma unroll
        for (int c = 0; c < 8; c++){
            X4[(size_t)(g * 8 + c) * stride + id] = x;
            x.x = fmaf(Pg[c].x, x.x, Sg[c].x);
            x.y = fmaf(Pg[c].y, x.y, Sg[c].y);
            x.z = fmaf(Pg[c].z, x.z, Sg[c].z);
            x.w = fmaf(Pg[c].w, x.w, Sg[c].w);
        }
    }
}

// ---------------------------------------------------------------------------
// Pass 3: final scan + output. All loads/stores coalesced from (B,L,H).
// y = Σ C'_n x'_n + D·u, C'_n = C_n*(am_n-1)*B_n/A_n; two 4-deep y chains.
// ---------------------------------------------------------------------------
__global__ __launch_bounds__(128) void scan_final_kernel(
        const float* __restrict__ Alog, const float* __restrict__ Bp,
        const float* __restrict__ Cp, const float* __restrict__ Dp,
        const float* __restrict__ u, float* __restrict__ out){
    const int tid = threadIdx.x;
    const int s = blockIdx.x * 128 + tid;
    const int chunk = blockIdx.y;
    const int b = s >> 10;
    const int h = s & 1023;

    u64 am2[8], c2[8], x2[8];
    #pragma unroll
    for (int i = 0; i < 8; i++){
        const float A0 = -expf(__ldg(Alog + h * NST + 2 * i));
        const float A1 = -expf(__ldg(Alog + h * NST + 2 * i + 1));
        const float am0 = exp2f(0.02f * A0 * LOG2E);
        const float am1 = exp2f(0.02f * A1 * LOG2E);
        am2[i] = f2u(am0, am1);
        const float s0 = (am0 - 1.f) * __ldg(Bp + h * NST + 2 * i) / A0;
        const float s1 = (am1 - 1.f) * __ldg(Bp + h * NST + 2 * i + 1) / A1;
        c2[i] = f2u(__ldg(Cp + h * NST + 2 * i) * s0,
                    __ldg(Cp + h * NST + 2 * i + 1) * s1);
    }
    const float Dh = __ldg(Dp + h);

    {   // initial state
        const float4* Xq = (const float4*)(g_Xin + ((size_t)chunk * NCH + s) * NST);
        #pragma unroll
        for (int i = 0; i < 4; i++){
            const float4 v = Xq[i];
            x2[2 * i]     = f2u(v.x, v.y);
            x2[2 * i + 1] = f2u(v.z, v.w);
        }
    }

    const size_t base = ((size_t)(b * LSEQ + chunk * CHLEN)) * HDIM + h;
    const float* up = u + base;
    const float* dp = g_dt + base;
    float* op = out + base;

    #pragma unroll 2
    for (int t = 0; t < CHLEN; t += 4){
        float uu[4], dv[4];
        #pragma unroll
        for (int j = 0; j < 4; j++){
            uu[j] = __ldg(up + (size_t)(t + j) * HDIM);
            dv[j] = __ldg(dp + (size_t)(t + j) * HDIM);
        }
        #pragma unroll
        for (int j = 0; j < 4; j++){
            if (dv[j] == DT_MAX_V){
                const u64 u2v = f2u(uu[j], uu[j]);
                #pragma unroll
                for (int i = 0; i < 8; i++)
                    x2[i] = ffma2(x2[i], am2[i], u2v);
            } else {
                slow_step(x2, am2, Alog, h, dv[j], uu[j]);
            }
            u64 ya = 0ull, yb = 0ull;
            #pragma unroll
            for (int i = 0; i < 4; i++) ya = ffma2(c2[i], x2[i], ya);
            #pragma unroll
            for (int i = 4; i < 8; i++) yb = ffma2(c2[i], x2[i], yb);
            const float2 va = u2f(ya);
            const float2 vb = u2f(yb);
            op[(size_t)(t + j) * HDIM] = fmaf(Dh, uu[j], (va.x + va.y) + (vb.x + vb.y));
        }
    }
}

// ---------------------------------------------------------------------------
extern "C" void kernel_launch(void* const* d_in, const int* in_sizes, int n_in,
                              void* d_out, int out_size){
    const float* u    = (const float*)d_in[0];
    const float* Alog = (const float*)d_in[1];
    const float* Bp   = (const float*)d_in[2];
    const float* Cp   = (const float*)d_in[3];
    const float* Dp   = (const float*)d_in[4];
    const float* Wdt  = (const float*)d_in[5];
    const float* bdt  = (const float*)d_in[6];
    float* out = (float*)d_out;

    cudaFuncSetAttribute(gemm_tf32_kernel,
                         cudaFuncAttributeMaxDynamicSharedMemorySize, 65536);

    dim3 ggrid(HDIM / 128, MROWS / 128);            // (8, 32)
    gemm_tf32_kernel<<<ggrid, 256, 65536>>>(u, Wdt, bdt);

    scan_reduce_kernel<<<dim3(NCH / 128, NCHUNK), 128>>>(Alog, u);
    scan_stitch_kernel<<<NCH * NST / 4 / 256, 256>>>();
    scan_final_kernel<<<dim3(NCH / 128, NCHUNK), 128>>>(Alog, Bp, Cp, Dp, u, out);
}

// round 5
// speedup vs baseline: 1.2462x; 1.2097x over previous
#include <cuda_runtime.h>

#define BATCH 2
#define LSEQ 2048
#define HDIM 1024
#define NST 16
#define MROWS (BATCH*LSEQ)     // 4096
#define DT_MIN_V 0.001f
#define DT_MAX_V 0.02f
#define NCHUNK 64
#define CHLEN (LSEQ/NCHUNK)    // 32
#define NCH (BATCH*HDIM)       // 2048
#define LOG2E 1.4426950408889634f

// Scratch (__device__ globals: allocation-free rule)
__device__ float g_dt [BATCH*LSEQ*HDIM];       // (B,L,H) — natural layout
__device__ float g_P  [NCHUNK*NCH*NST];
__device__ float g_S  [NCHUNK*NCH*NST];
__device__ float g_Xin[NCHUNK*NCH*NST];

typedef unsigned long long u64;

__device__ __forceinline__ u64 ffma2(u64 a, u64 b, u64 c){
    u64 d;
    asm("fma.rn.f32x2 %0, %1, %2, %3;" : "=l"(d) : "l"(a), "l"(b), "l"(c));
    return d;
}
__device__ __forceinline__ u64 f2u(float x, float y){
    u64 v; asm("mov.b64 %0, {%1, %2};" : "=l"(v) : "f"(x), "f"(y)); return v;
}
__device__ __forceinline__ float2 u2f(u64 v){
    float2 r; asm("mov.b64 {%0, %1}, %2;" : "=f"(r.x), "=f"(r.y) : "l"(v)); return r;
}

// ---------------------------------------------------------------------------
// TF32 tensor-core GEMM (unchanged): log_dt = U·Wᵀ + b; dt = clamp(exp()).
// Writes g_dt in (B,L,H) layout.
// ---------------------------------------------------------------------------
__device__ __forceinline__ void cp16(float* s, const float* g){
    unsigned sa = (unsigned)__cvta_generic_to_shared(s);
    asm volatile("cp.async.cg.shared.global [%0], [%1], 16;" :: "r"(sa), "l"(g));
}
__device__ __forceinline__ void ldsm4(unsigned* r, unsigned addr){
    asm volatile("ldmatrix.sync.aligned.m8n8.x4.shared.b16 {%0,%1,%2,%3}, [%4];"
        : "=r"(r[0]), "=r"(r[1]), "=r"(r[2]), "=r"(r[3]) : "r"(addr));
}
__device__ __forceinline__ void mma_tf32(float* d, const unsigned* a,
                                         unsigned b0, unsigned b1){
    asm volatile(
        "mma.sync.aligned.m16n8k8.row.col.f32.tf32.tf32.f32 "
        "{%0,%1,%2,%3}, {%4,%5,%6,%7}, {%8,%9}, {%0,%1,%2,%3};"
        : "+f"(d[0]), "+f"(d[1]), "+f"(d[2]), "+f"(d[3])
        : "r"(a[0]), "r"(a[1]), "r"(a[2]), "r"(a[3]), "r"(b0), "r"(b1));
}

__global__ __launch_bounds__(256) void gemm_tf32_kernel(
        const float* __restrict__ U, const float* __restrict__ W,
        const float* __restrict__ bias){
    extern __shared__ float smem[];
    const int tid  = threadIdx.x;
    const int lane = tid & 31;
    const int wid  = tid >> 5;
    const int wm   = wid & 1;
    const int wn   = wid >> 1;
    const int bm   = blockIdx.y * 128;
    const int bn   = blockIdx.x * 128;

    float acc[4][4][4];
    #pragma unroll
    for (int i = 0; i < 4; i++)
        #pragma unroll
        for (int j = 0; j < 4; j++)
            #pragma unroll
            for (int r = 0; r < 4; r++) acc[i][j][r] = 0.f;

    const int lrow = tid >> 3;
    const int lkc  = tid & 7;

    unsigned smemBase = (unsigned)__cvta_generic_to_shared(smem);
    const unsigned aRowOff = (unsigned)((wm * 64 + (lane & 15)) * 128);
    const unsigned bRowOff = (unsigned)((wn * 32 + ((lane & 16) >> 1) + (lane & 7)) * 128);
    int physA[4], physB[4];
    #pragma unroll
    for (int ks = 0; ks < 4; ks++){
        physA[ks] = ((2 * ks + (lane >> 4)) ^ (lane & 7)) * 16;
        physB[ks] = ((2 * ks + ((lane >> 3) & 1)) ^ (lane & 7)) * 16;
    }

    #define LOAD_TILE(KT, STG) do {                                            \
        float* A_s = smem + (STG) * 8192;                                      \
        float* B_s = A_s + 4096;                                               \
        _Pragma("unroll")                                                      \
        for (int i = 0; i < 4; i++){                                           \
            int row  = lrow + i * 32;                                          \
            int phys = lkc ^ (row & 7);                                        \
            cp16(A_s + row * 32 + phys * 4,                                    \
                 U + (size_t)(bm + row) * 1024 + (KT) * 32 + lkc * 4);         \
            cp16(B_s + row * 32 + phys * 4,                                    \
                 W + (size_t)(bn + row) * 1024 + (KT) * 32 + lkc * 4);         \
        }                                                                      \
        asm volatile("cp.async.commit_group;");                                \
    } while (0)

    LOAD_TILE(0, 0);

    for (int kt = 0; kt < 32; kt++){
        const int cur = kt & 1;
        if (kt < 31) LOAD_TILE(kt + 1, cur ^ 1);
        if (kt < 31) asm volatile("cp.async.wait_group 1;");
        else         asm volatile("cp.async.wait_group 0;");
        __syncthreads();

        unsigned aB = smemBase + cur * 32768 + aRowOff;
        unsigned bB = smemBase + cur * 32768 + 16384 + bRowOff;
        #pragma unroll
        for (int ks = 0; ks < 4; ks++){
            unsigned a[4][4], bb[2][4];
            #pragma unroll
            for (int mt = 0; mt < 4; mt++)
                ldsm4(a[mt], aB + mt * 16 * 128 + physA[ks]);
            #pragma unroll
            for (int tp = 0; tp < 2; tp++)
                ldsm4(bb[tp], bB + tp * 16 * 128 + physB[ks]);
            #pragma unroll
            for (int mt = 0; mt < 4; mt++)
                #pragma unroll
                for (int nt = 0; nt < 4; nt++)
                    mma_tf32(acc[mt][nt], a[mt],
                             bb[nt >> 1][(nt & 1) * 2], bb[nt >> 1][(nt & 1) * 2 + 1]);
        }
        __syncthreads();
    }

    const int rbase = bm + wm * 64 + (lane >> 2);
    const int gbase = bn + wn * 32 + 2 * (lane & 3);
    float bv[4][2];
    #pragma unroll
    for (int nt = 0; nt < 4; nt++){
        bv[nt][0] = __ldg(bias + gbase + nt * 8);
        bv[nt][1] = __ldg(bias + gbase + nt * 8 + 1);
    }
    #pragma unroll
    for (int mt = 0; mt < 4; mt++)
        #pragma unroll
        for (int nt = 0; nt < 4; nt++)
            #pragma unroll
            for (int rr = 0; rr < 2; rr++){
                const int m = rbase + mt * 16 + rr * 8;
                float2 o;
                float v0 = acc[mt][nt][rr * 2]     + bv[nt][0];
                float v1 = acc[mt][nt][rr * 2 + 1] + bv[nt][1];
                o.x = fminf(fmaxf(__expf(v0), DT_MIN_V), DT_MAX_V);
                o.y = fminf(fmaxf(__expf(v1), DT_MIN_V), DT_MAX_V);
                *(float2*)&g_dt[(size_t)m * HDIM + gbase + nt * 8] = o;
            }
}

// ---------------------------------------------------------------------------
// Pass 1: per-(channel,chunk) reduce. Thread = one channel-chunk.
// Fast path: all 8 dt in group clipped -> pure FFMA2. Rare path inline, one
// code copy (outer loop unroll 1, rare loop not unrolled, global reloads by
// dynamic index so register arrays stay const-indexed).
// ---------------------------------------------------------------------------
__global__ __launch_bounds__(128) void scan_reduce_kernel(
        const float* __restrict__ Alog, const float* __restrict__ u){
    const int tid = threadIdx.x;
    const int s = blockIdx.x * 128 + tid;
    const int chunk = blockIdx.y;
    const int b = s >> 10;
    const int h = s & 1023;

    u64 am2[8], x2[8];
    #pragma unroll
    for (int i = 0; i < 8; i++){
        const float A0 = -expf(__ldg(Alog + h * NST + 2 * i));
        const float A1 = -expf(__ldg(Alog + h * NST + 2 * i + 1));
        am2[i] = f2u(exp2f(0.02f * A0 * LOG2E), exp2f(0.02f * A1 * LOG2E));
        x2[i] = 0ull;
    }
    float dtsum = 0.f;

    const size_t base = ((size_t)(b * LSEQ + chunk * CHLEN)) * HDIM + h;
    const float* up = u + base;
    const float* dp = g_dt + base;

    #pragma unroll 1
    for (int t = 0; t < CHLEN; t += 8){
        float uu[8], dv[8];
        #pragma unroll
        for (int j = 0; j < 8; j++){
            uu[j] = __ldg(up + (size_t)(t + j) * HDIM);
            dv[j] = __ldg(dp + (size_t)(t + j) * HDIM);
        }
        bool fast = true;
        #pragma unroll
        for (int j = 0; j < 8; j++) fast &= (dv[j] == DT_MAX_V);

        if (fast){
            #pragma unroll
            for (int j = 0; j < 8; j++){
                dtsum += dv[j];
                const u64 u2v = f2u(uu[j], uu[j]);
                #pragma unroll
                for (int i = 0; i < 8; i++)
                    x2[i] = ffma2(x2[i], am2[i], u2v);
            }
        } else {
            #pragma unroll 1
            for (int jj = 0; jj < 8; jj++){
                const float dtv = __ldg(dp + (size_t)(t + jj) * HDIM);
                const float uv  = __ldg(up + (size_t)(t + jj) * HDIM);
                dtsum += dtv;
                #pragma unroll
                for (int i = 0; i < 8; i++){
                    float2 xv = u2f(x2[i]);
                    const float2 av = u2f(am2[i]);
                    {
                        const float A = -expf(__ldg(Alog + h * NST + 2 * i));
                        const float ab = exp2f(dtv * A * LOG2E);
                        xv.x = fmaf(xv.x, ab, (ab - 1.f) / (av.x - 1.f) * uv);
                    }
                    {
                        const float A = -expf(__ldg(Alog + h * NST + 2 * i + 1));
                        const float ab = exp2f(dtv * A * LOG2E);
                        xv.y = fmaf(xv.y, ab, (ab - 1.f) / (av.y - 1.f) * uv);
                    }
                    x2[i] = f2u(xv.x, xv.y);
                }
            }
        }
    }

    float* Pp = g_P + ((size_t)chunk * NCH + s) * NST;
    float* Sp = g_S + ((size_t)chunk * NCH + s) * NST;
    #pragma unroll
    for (int i = 0; i < 8; i++){
        const float A0 = -expf(__ldg(Alog + h * NST + 2 * i));
        const float A1 = -expf(__ldg(Alog + h * NST + 2 * i + 1));
        const float2 xv = u2f(x2[i]);
        Pp[2 * i]     = exp2f(A0 * LOG2E * dtsum);
        Pp[2 * i + 1] = exp2f(A1 * LOG2E * dtsum);
        Sp[2 * i]     = xv.x;
        Sp[2 * i + 1] = xv.y;
    }
}

// ---------------------------------------------------------------------------
// Pass 2: stitch boundary states (unchanged).
// ---------------------------------------------------------------------------
__global__ void scan_stitch_kernel(){
    const int id = blockIdx.x * blockDim.x + threadIdx.x;  // 0..8191
    const float4* P4 = (const float4*)g_P;
    const float4* S4 = (const float4*)g_S;
    float4* X4 = (float4*)g_Xin;
    const int stride = NCH * NST / 4;
    float4 x = make_float4(0.f, 0.f, 0.f, 0.f);
    #pragma unroll
    for (int g = 0; g < 8; g++){
        float4 Pg[8], Sg[8];
        #pragma unroll
        for (int c = 0; c < 8; c++){
            Pg[c] = P4[(size_t)(g * 8 + c) * stride + id];
            Sg[c] = S4[(size_t)(g * 8 + c) * stride + id];
        }
        #pragma unroll
        for (int c = 0; c < 8; c++){
            X4[(size_t)(g * 8 + c) * stride + id] = x;
            x.x = fmaf(Pg[c].x, x.x, Sg[c].x);
            x.y = fmaf(Pg[c].y, x.y, Sg[c].y);
            x.z = fmaf(Pg[c].z, x.z, Sg[c].z);
            x.w = fmaf(Pg[c].w, x.w, Sg[c].w);
        }
    }
}

// ---------------------------------------------------------------------------
// Pass 3: final scan + output, same fast/rare structure as pass 1.
// ---------------------------------------------------------------------------
__global__ __launch_bounds__(128) void scan_final_kernel(
        const float* __restrict__ Alog, const float* __restrict__ Bp,
        const float* __restrict__ Cp, const float* __restrict__ Dp,
        const float* __restrict__ u, float* __restrict__ out){
    const int tid = threadIdx.x;
    const int s = blockIdx.x * 128 + tid;
    const int chunk = blockIdx.y;
    const int b = s >> 10;
    const int h = s & 1023;

    u64 am2[8], c2[8], x2[8];
    #pragma unroll
    for (int i = 0; i < 8; i++){
        const float A0 = -expf(__ldg(Alog + h * NST + 2 * i));
        const float A1 = -expf(__ldg(Alog + h * NST + 2 * i + 1));
        const float am0 = exp2f(0.02f * A0 * LOG2E);
        const float am1 = exp2f(0.02f * A1 * LOG2E);
        am2[i] = f2u(am0, am1);
        const float s0 = (am0 - 1.f) * __ldg(Bp + h * NST + 2 * i) / A0;
        const float s1 = (am1 - 1.f) * __ldg(Bp + h * NST + 2 * i + 1) / A1;
        c2[i] = f2u(__ldg(Cp + h * NST + 2 * i) * s0,
                    __ldg(Cp + h * NST + 2 * i + 1) * s1);
    }
    const float Dh = __ldg(Dp + h);

    {
        const float4* Xq = (const float4*)(g_Xin + ((size_t)chunk * NCH + s) * NST);
        #pragma unroll
        for (int i = 0; i < 4; i++){
            const float4 v = Xq[i];
            x2[2 * i]     = f2u(v.x, v.y);
            x2[2 * i + 1] = f2u(v.z, v.w);
        }
    }

    const size_t base = ((size_t)(b * LSEQ + chunk * CHLEN)) * HDIM + h;
    const float* up = u + base;
    const float* dp = g_dt + base;
    float* op = out + base;

    #pragma unroll 1
    for (int t = 0; t < CHLEN; t += 8){
        float uu[8], dv[8];
        #pragma unroll
        for (int j = 0; j < 8; j++){
            uu[j] = __ldg(up + (size_t)(t + j) * HDIM);
            dv[j] = __ldg(dp + (size_t)(t + j) * HDIM);
        }
        bool fast = true;
        #pragma unroll
        for (int j = 0; j < 8; j++) fast &= (dv[j] == DT_MAX_V);

        if (fast){
            #pragma unroll
            for (int j = 0; j < 8; j++){
                const u64 u2v = f2u(uu[j], uu[j]);
                #pragma unroll
                for (int i = 0; i < 8; i++)
                    x2[i] = ffma2(x2[i], am2[i], u2v);
                u64 ya = 0ull, yb = 0ull;
                #pragma unroll
                for (int i = 0; i < 4; i++) ya = ffma2(c2[i], x2[i], ya);
                #pragma unroll
                for (int i = 4; i < 8; i++) yb = ffma2(c2[i], x2[i], yb);
                const float2 va = u2f(ya);
                const float2 vb = u2f(yb);
                op[(size_t)(t + j) * HDIM] = fmaf(Dh, uu[j], (va.x + va.y) + (vb.x + vb.y));
            }
        } else {
            #pragma unroll 1
            for (int jj = 0; jj < 8; jj++){
                const float dtv = __ldg(dp + (size_t)(t + jj) * HDIM);
                const float uv  = __ldg(up + (size_t)(t + jj) * HDIM);
                #pragma unroll
                for (int i = 0; i < 8; i++){
                    float2 xv = u2f(x2[i]);
                    const float2 av = u2f(am2[i]);
                    {
                        const float A = -expf(__ldg(Alog + h * NST + 2 * i));
                        const float ab = exp2f(dtv * A * LOG2E);
                        xv.x = fmaf(xv.x, ab, (ab - 1.f) / (av.x - 1.f) * uv);
                    }
                    {
                        const float A = -expf(__ldg(Alog + h * NST + 2 * i + 1));
                        const float ab = exp2f(dtv * A * LOG2E);
                        xv.y = fmaf(xv.y, ab, (ab - 1.f) / (av.y - 1.f) * uv);
                    }
                    x2[i] = f2u(xv.x, xv.y);
                }
                u64 ya = 0ull, yb = 0ull;
                #pragma unroll
                for (int i = 0; i < 4; i++) ya = ffma2(c2[i], x2[i], ya);
                #pragma unroll
                for (int i = 4; i < 8; i++) yb = ffma2(c2[i], x2[i], yb);
                const float2 va = u2f(ya);
                const float2 vb = u2f(yb);
                op[(size_t)(t + jj) * HDIM] = fmaf(Dh, uv, (va.x + va.y) + (vb.x + vb.y));
            }
        }
    }
}

// ---------------------------------------------------------------------------
extern "C" void kernel_launch(void* const* d_in, const int* in_sizes, int n_in,
                              void* d_out, int out_size){
    const float* u    = (const float*)d_in[0];
    const float* Alog = (const float*)d_in[1];
    const float* Bp   = (const float*)d_in[2];
    const float* Cp   = (const float*)d_in[3];
    const float* Dp   = (const float*)d_in[4];
    const float* Wdt  = (const float*)d_in[5];
    const float* bdt  = (const float*)d_in[6];
    float* out = (float*)d_out;

    cudaFuncSetAttribute(gemm_tf32_kernel,
                         cudaFuncAttributeMaxDynamicSharedMemorySize, 65536);

    dim3 ggrid(HDIM / 128, MROWS / 128);            // (8, 32)
    gemm_tf32_kernel<<<ggrid, 256, 65536>>>(u, Wdt, bdt);

    scan_reduce_kernel<<<dim3(NCH / 128, NCHUNK), 128>>>(Alog, u);
    scan_stitch_kernel<<<NCH * NST / 4 / 256, 256>>>();
    scan_final_kernel<<<dim3(NCH / 128, NCHUNK), 128>>>(Alog, Bp, Cp, Dp, u, out);
}

// round 6
// speedup vs baseline: 1.3132x; 1.0538x over previous
#include <cuda_runtime.h>

#define BATCH 2
#define LSEQ 2048
#define HDIM 1024
#define NST 16
#define MROWS (BATCH*LSEQ)     // 4096
#define DT_MIN_V 0.001f
#define DT_MAX_V 0.02f
#define NCHUNK 128
#define CHLEN (LSEQ/NCHUNK)    // 16
#define NCH (BATCH*HDIM)       // 2048
#define LOG2E 1.4426950408889634f

// Scratch (__device__ globals: allocation-free rule)
__device__ float2 g_du[BATCH*LSEQ*HDIM];       // (B,L,H) packed {dt, u}
__device__ float  g_P [NCHUNK*NCH*NST];
__device__ float  g_S [NCHUNK*NCH*NST];
__device__ float  g_Xin[NCHUNK*NCH*NST];

typedef unsigned long long u64;

__device__ __forceinline__ u64 ffma2(u64 a, u64 b, u64 c){
    u64 d;
    asm("fma.rn.f32x2 %0, %1, %2, %3;" : "=l"(d) : "l"(a), "l"(b), "l"(c));
    return d;
}
__device__ __forceinline__ u64 f2u(float x, float y){
    u64 v; asm("mov.b64 %0, {%1, %2};" : "=l"(v) : "f"(x), "f"(y)); return v;
}
__device__ __forceinline__ float2 u2f(u64 v){
    float2 r; asm("mov.b64 {%0, %1}, %2;" : "=f"(r.x), "=f"(r.y) : "l"(v)); return r;
}

// ---------------------------------------------------------------------------
// TF32 tensor-core GEMM: log_dt = U·Wᵀ + b; dt = clamp(exp()).
// Epilogue writes packed g_du[(b,l,h)] = {dt, u}.
// ---------------------------------------------------------------------------
__device__ __forceinline__ void cp16(float* s, const float* g){
    unsigned sa = (unsigned)__cvta_generic_to_shared(s);
    asm volatile("cp.async.cg.shared.global [%0], [%1], 16;" :: "r"(sa), "l"(g));
}
__device__ __forceinline__ void ldsm4(unsigned* r, unsigned addr){
    asm volatile("ldmatrix.sync.aligned.m8n8.x4.shared.b16 {%0,%1,%2,%3}, [%4];"
        : "=r"(r[0]), "=r"(r[1]), "=r"(r[2]), "=r"(r[3]) : "r"(addr));
}
__device__ __forceinline__ void mma_tf32(float* d, const unsigned* a,
                                         unsigned b0, unsigned b1){
    asm volatile(
        "mma.sync.aligned.m16n8k8.row.col.f32.tf32.tf32.f32 "
        "{%0,%1,%2,%3}, {%4,%5,%6,%7}, {%8,%9}, {%0,%1,%2,%3};"
        : "+f"(d[0]), "+f"(d[1]), "+f"(d[2]), "+f"(d[3])
        : "r"(a[0]), "r"(a[1]), "r"(a[2]), "r"(a[3]), "r"(b0), "r"(b1));
}

__global__ __launch_bounds__(256) void gemm_tf32_kernel(
        const float* __restrict__ U, const float* __restrict__ W,
        const float* __restrict__ bias){
    extern __shared__ float smem[];
    const int tid  = threadIdx.x;
    const int lane = tid & 31;
    const int wid  = tid >> 5;
    const int wm   = wid & 1;
    const int wn   = wid >> 1;
    const int bm   = blockIdx.y * 128;
    const int bn   = blockIdx.x * 128;

    float acc[4][4][4];
    #pragma unroll
    for (int i = 0; i < 4; i++)
        #pragma unroll
        for (int j = 0; j < 4; j++)
            #pragma unroll
            for (int r = 0; r < 4; r++) acc[i][j][r] = 0.f;

    const int lrow = tid >> 3;
    const int lkc  = tid & 7;

    unsigned smemBase = (unsigned)__cvta_generic_to_shared(smem);
    const unsigned aRowOff = (unsigned)((wm * 64 + (lane & 15)) * 128);
    const unsigned bRowOff = (unsigned)((wn * 32 + ((lane & 16) >> 1) + (lane & 7)) * 128);
    int physA[4], physB[4];
    #pragma unroll
    for (int ks = 0; ks < 4; ks++){
        physA[ks] = ((2 * ks + (lane >> 4)) ^ (lane & 7)) * 16;
        physB[ks] = ((2 * ks + ((lane >> 3) & 1)) ^ (lane & 7)) * 16;
    }

    #define LOAD_TILE(KT, STG) do {                                            \
        float* A_s = smem + (STG) * 8192;                                      \
        float* B_s = A_s + 4096;                                               \
        _Pragma("unroll")                                                      \
        for (int i = 0; i < 4; i++){                                           \
            int row  = lrow + i * 32;                                          \
            int phys = lkc ^ (row & 7);                                        \
            cp16(A_s + row * 32 + phys * 4,                                    \
                 U + (size_t)(bm + row) * 1024 + (KT) * 32 + lkc * 4);         \
            cp16(B_s + row * 32 + phys * 4,                                    \
                 W + (size_t)(bn + row) * 1024 + (KT) * 32 + lkc * 4);         \
        }                                                                      \
        asm volatile("cp.async.commit_group;");                                \
    } while (0)

    LOAD_TILE(0, 0);

    for (int kt = 0; kt < 32; kt++){
        const int cur = kt & 1;
        if (kt < 31) LOAD_TILE(kt + 1, cur ^ 1);
        if (kt < 31) asm volatile("cp.async.wait_group 1;");
        else         asm volatile("cp.async.wait_group 0;");
        __syncthreads();

        unsigned aB = smemBase + cur * 32768 + aRowOff;
        unsigned bB = smemBase + cur * 32768 + 16384 + bRowOff;
        #pragma unroll
        for (int ks = 0; ks < 4; ks++){
            unsigned a[4][4], bb[2][4];
            #pragma unroll
            for (int mt = 0; mt < 4; mt++)
                ldsm4(a[mt], aB + mt * 16 * 128 + physA[ks]);
            #pragma unroll
            for (int tp = 0; tp < 2; tp++)
                ldsm4(bb[tp], bB + tp * 16 * 128 + physB[ks]);
            #pragma unroll
            for (int mt = 0; mt < 4; mt++)
                #pragma unroll
                for (int nt = 0; nt < 4; nt++)
                    mma_tf32(acc[mt][nt], a[mt],
                             bb[nt >> 1][(nt & 1) * 2], bb[nt >> 1][(nt & 1) * 2 + 1]);
        }
        __syncthreads();
    }

    const int rbase = bm + wm * 64 + (lane >> 2);
    const int gbase = bn + wn * 32 + 2 * (lane & 3);
    float bv[4][2];
    #pragma unroll
    for (int nt = 0; nt < 4; nt++){
        bv[nt][0] = __ldg(bias + gbase + nt * 8);
        bv[nt][1] = __ldg(bias + gbase + nt * 8 + 1);
    }
    #pragma unroll
    for (int mt = 0; mt < 4; mt++)
        #pragma unroll
        for (int nt = 0; nt < 4; nt++)
            #pragma unroll
            for (int rr = 0; rr < 2; rr++){
                const int m = rbase + mt * 16 + rr * 8;
                const int g0 = gbase + nt * 8;
                float v0 = acc[mt][nt][rr * 2]     + bv[nt][0];
                float v1 = acc[mt][nt][rr * 2 + 1] + bv[nt][1];
                v0 = fminf(fmaxf(__expf(v0), DT_MIN_V), DT_MAX_V);
                v1 = fminf(fmaxf(__expf(v1), DT_MIN_V), DT_MAX_V);
                const float2 uv = *(const float2*)&U[(size_t)m * HDIM + g0];
                float4 w;
                w.x = v0; w.y = uv.x;   // {dt0, u0}
                w.z = v1; w.w = uv.y;   // {dt1, u1}
                *(float4*)&g_du[(size_t)m * HDIM + g0] = w;
            }
}

// ---------------------------------------------------------------------------
// Fast step: x'_n = x'_n * am_n + u   (all 16 states, f32x2)
// Slow step: x'_n = x'_n * abar_n + ((abar_n-1)/(am_n-1)) * u
// Both fully inline, register-only.
// ---------------------------------------------------------------------------
#define FAST_STEP(uu) do {                                                     \
    const u64 _u2 = f2u((uu), (uu));                                           \
    _Pragma("unroll")                                                          \
    for (int _i = 0; _i < 8; _i++) x2[_i] = ffma2(x2[_i], am2[_i], _u2);       \
} while (0)

#define SLOW_STEP(dtv, uv) do {                                                \
    _Pragma("unroll")                                                          \
    for (int _i = 0; _i < 8; _i++){                                            \
        float2 _xv = u2f(x2[_i]);                                              \
        const float2 _av = u2f(am2[_i]);                                       \
        {                                                                      \
            const float _A = -expf(__ldg(Alog + h * NST + 2 * _i));            \
            const float _ab = exp2f((dtv) * _A * LOG2E);                       \
            _xv.x = fmaf(_xv.x, _ab, (_ab - 1.f) / (_av.x - 1.f) * (uv));      \
        }                                                                      \
        {                                                                      \
            const float _A = -expf(__ldg(Alog + h * NST + 2 * _i + 1));        \
            const float _ab = exp2f((dtv) * _A * LOG2E);                       \
            _xv.y = fmaf(_xv.y, _ab, (_ab - 1.f) / (_av.y - 1.f) * (uv));      \
        }                                                                      \
        x2[_i] = f2u(_xv.x, _xv.y);                                            \
    }                                                                          \
} while (0)

// ---------------------------------------------------------------------------
// Pass 1: per-(channel,chunk) reduce. Whole 16-step tile loaded to registers
// up front (16x LDG.64, MLP=16) — one latency exposure per thread.
// ---------------------------------------------------------------------------
__global__ __launch_bounds__(128) void scan_reduce_kernel(
        const float* __restrict__ Alog){
    const int tid = threadIdx.x;
    const int s = blockIdx.x * 128 + tid;
    const int chunk = blockIdx.y;
    const int b = s >> 10;
    const int h = s & 1023;

    u64 am2[8], x2[8];
    #pragma unroll
    for (int i = 0; i < 8; i++){
        const float A0 = -expf(__ldg(Alog + h * NST + 2 * i));
        const float A1 = -expf(__ldg(Alog + h * NST + 2 * i + 1));
        am2[i] = f2u(exp2f(0.02f * A0 * LOG2E), exp2f(0.02f * A1 * LOG2E));
        x2[i] = 0ull;
    }

    const size_t base = ((size_t)(b * LSEQ + chunk * CHLEN)) * HDIM + h;
    float2 d[CHLEN];
    #pragma unroll
    for (int j = 0; j < CHLEN; j++)
        d[j] = __ldg((const float2*)&g_du[base + (size_t)j * HDIM]);

    float dtsum = 0.f;
    bool fast = true;
    #pragma unroll
    for (int j = 0; j < CHLEN; j++){ fast &= (d[j].x == DT_MAX_V); dtsum += d[j].x; }

    if (fast){
        #pragma unroll
        for (int j = 0; j < CHLEN; j++) FAST_STEP(d[j].y);
    } else {
        #pragma unroll
        for (int j = 0; j < CHLEN; j++){
            if (d[j].x == DT_MAX_V) FAST_STEP(d[j].y);
            else                    SLOW_STEP(d[j].x, d[j].y);
        }
    }

    float* Pp = g_P + ((size_t)chunk * NCH + s) * NST;
    float* Sp = g_S + ((size_t)chunk * NCH + s) * NST;
    #pragma unroll
    for (int i = 0; i < 8; i++){
        const float A0 = -expf(__ldg(Alog + h * NST + 2 * i));
        const float A1 = -expf(__ldg(Alog + h * NST + 2 * i + 1));
        const float2 xv = u2f(x2[i]);
        *(float2*)(Pp + 2 * i) = make_float2(exp2f(A0 * LOG2E * dtsum),
                                             exp2f(A1 * LOG2E * dtsum));
        *(float2*)(Sp + 2 * i) = make_float2(xv.x, xv.y);
    }
}

// ---------------------------------------------------------------------------
// Pass 2: stitch 128-deep boundary chain. 16 groups of (8 batched loads +
// 8 sequential folds).
// ---------------------------------------------------------------------------
__global__ void scan_stitch_kernel(){
    const int id = blockIdx.x * blockDim.x + threadIdx.x;  // 0..8191
    const float4* P4 = (const float4*)g_P;
    const float4* S4 = (const float4*)g_S;
    float4* X4 = (float4*)g_Xin;
    const int stride = NCH * NST / 4;                      // 8192 float4/chunk
    float4 x = make_float4(0.f, 0.f, 0.f, 0.f);
    #pragma unroll 1
    for (int g = 0; g < NCHUNK / 8; g++){
        float4 Pg[8], Sg[8];
        #pragma unroll
        for (int c = 0; c < 8; c++){
            Pg[c] = P4[(size_t)(g * 8 + c) * stride + id];
            Sg[c] = S4[(size_t)(g * 8 + c) * stride + id];
        }
        #pragma unroll
        for (int c = 0; c < 8; c++){
            X4[(size_t)(g * 8 + c) * stride + id] = x;
            x.x = fmaf(Pg[c].x, x.x, Sg[c].x);
            x.y = fmaf(Pg[c].y, x.y, Sg[c].y);
            x.z = fmaf(Pg[c].z, x.z, Sg[c].z);
            x.w = fmaf(Pg[c].w, x.w, Sg[c].w);
        }
    }
}

// ---------------------------------------------------------------------------
// Pass 3: final scan + output, register-resident tile, same as pass 1 plus y.
// ---------------------------------------------------------------------------
__global__ __launch_bounds__(128) void scan_final_kernel(
        const float* __restrict__ Alog, const float* __restrict__ Bp,
        const float* __restrict__ Cp, const float* __restrict__ Dp,
        float* __restrict__ out){
    const int tid = threadIdx.x;
    const int s = blockIdx.x * 128 + tid;
    const int chunk = blockIdx.y;
    const int b = s >> 10;
    const int h = s & 1023;

    const size_t base = ((size_t)(b * LSEQ + chunk * CHLEN)) * HDIM + h;
    float2 d[CHLEN];
    #pragma unroll
    for (int j = 0; j < CHLEN; j++)
        d[j] = __ldg((const float2*)&g_du[base + (size_t)j * HDIM]);

    u64 am2[8], c2[8], x2[8];
    #pragma unroll
    for (int i = 0; i < 8; i++){
        const float A0 = -expf(__ldg(Alog + h * NST + 2 * i));
        const float A1 = -expf(__ldg(Alog + h * NST + 2 * i + 1));
        const float am0 = exp2f(0.02f * A0 * LOG2E);
        const float am1 = exp2f(0.02f * A1 * LOG2E);
        am2[i] = f2u(am0, am1);
        const float s0 = (am0 - 1.f) * __ldg(Bp + h * NST + 2 * i) / A0;
        const float s1 = (am1 - 1.f) * __ldg(Bp + h * NST + 2 * i + 1) / A1;
        c2[i] = f2u(__ldg(Cp + h * NST + 2 * i) * s0,
                    __ldg(Cp + h * NST + 2 * i + 1) * s1);
    }
    const float Dh = __ldg(Dp + h);

    {
        const float4* Xq = (const float4*)(g_Xin + ((size_t)chunk * NCH + s) * NST);
        #pragma unroll
        for (int i = 0; i < 4; i++){
            const float4 v = Xq[i];
            x2[2 * i]     = f2u(v.x, v.y);
            x2[2 * i + 1] = f2u(v.z, v.w);
        }
    }

    float* op = out + base;

    bool fast = true;
    #pragma unroll
    for (int j = 0; j < CHLEN; j++) fast &= (d[j].x == DT_MAX_V);

    #define Y_EMIT(j, uv) do {                                                 \
        u64 ya = 0ull, yb = 0ull;                                              \
        _Pragma("unroll")                                                      \
        for (int _i = 0; _i < 4; _i++) ya = ffma2(c2[_i], x2[_i], ya);         \
        _Pragma("unroll")                                                      \
        for (int _i = 4; _i < 8; _i++) yb = ffma2(c2[_i], x2[_i], yb);         \
        const float2 _va = u2f(ya);                                            \
        const float2 _vb = u2f(yb);                                            \
        op[(size_t)(j) * HDIM] = fmaf(Dh, (uv), (_va.x + _va.y) + (_vb.x + _vb.y)); \
    } while (0)

    if (fast){
        #pragma unroll
        for (int j = 0; j < CHLEN; j++){
            FAST_STEP(d[j].y);
            Y_EMIT(j, d[j].y);
        }
    } else {
        #pragma unroll
        for (int j = 0; j < CHLEN; j++){
            if (d[j].x == DT_MAX_V) FAST_STEP(d[j].y);
            else                    SLOW_STEP(d[j].x, d[j].y);
            Y_EMIT(j, d[j].y);
        }
    }
    #undef Y_EMIT
}

// ---------------------------------------------------------------------------
extern "C" void kernel_launch(void* const* d_in, const int* in_sizes, int n_in,
                              void* d_out, int out_size){
    const float* u    = (const float*)d_in[0];
    const float* Alog = (const float*)d_in[1];
    const float* Bp   = (const float*)d_in[2];
    const float* Cp   = (const float*)d_in[3];
    const float* Dp   = (const float*)d_in[4];
    const float* Wdt  = (const float*)d_in[5];
    const float* bdt  = (const float*)d_in[6];
    float* out = (float*)d_out;

    cudaFuncSetAttribute(gemm_tf32_kernel,
                         cudaFuncAttributeMaxDynamicSharedMemorySize, 65536);

    dim3 ggrid(HDIM / 128, MROWS / 128);            // (8, 32)
    gemm_tf32_kernel<<<ggrid, 256, 65536>>>(u, Wdt, bdt);

    scan_reduce_kernel<<<dim3(NCH / 128, NCHUNK), 128>>>(Alog);
    scan_stitch_kernel<<<NCH * NST / 4 / 256, 256>>>();
    scan_final_kernel<<<dim3(NCH / 128, NCHUNK), 128>>>(Alog, Bp, Cp, Dp, out);
}

// round 7
// speedup vs baseline: 1.8191x; 1.3852x over previous
#include <cuda_runtime.h>

#define BATCH 2
#define LSEQ 2048
#define HDIM 1024
#define NST 16
#define MROWS (BATCH*LSEQ)     // 4096
#define DT_MIN_V 0.001f
#define DT_MAX_V 0.02f
#define NCHUNK 128
#define CHLEN (LSEQ/NCHUNK)    // 16
#define NCH (BATCH*HDIM)       // 2048
#define LOG2E 1.4426950408889634f

typedef unsigned long long u64;

// Scratch (__device__ globals: allocation-free rule)
__device__ float2 g_du[BATCH*LSEQ*HDIM];       // (B,L,H) packed {dt, u}
// P/S/Xin in transposed layout [chunk][n][s] for coalesced access
__device__ float  g_P  [NCHUNK*NST*NCH];
__device__ float  g_S  [NCHUNK*NST*NCH];
__device__ float  g_Xin[NCHUNK*NST*NCH];
// Per-channel constant tables, packed pairs, layout [pair i][h] (coalesced)
__device__ u64 g_am2T[8*HDIM];   // {exp(0.02*A_2i), exp(0.02*A_2i+1)}
__device__ u64 g_al2T[8*HDIM];   // {A*log2e pairs}
__device__ u64 g_c2T [8*HDIM];   // {C_n*(am_n-1)*B_n/A_n pairs}

__device__ __forceinline__ u64 ffma2(u64 a, u64 b, u64 c){
    u64 d;
    asm("fma.rn.f32x2 %0, %1, %2, %3;" : "=l"(d) : "l"(a), "l"(b), "l"(c));
    return d;
}
__device__ __forceinline__ u64 f2u(float x, float y){
    u64 v; asm("mov.b64 %0, {%1, %2};" : "=l"(v) : "f"(x), "f"(y)); return v;
}
__device__ __forceinline__ float2 u2f(u64 v){
    float2 r; asm("mov.b64 {%0, %1}, %2;" : "=f"(r.x), "=f"(r.y) : "l"(v)); return r;
}

// ---------------------------------------------------------------------------
// Precompute per-channel constants (runs once, 1024 threads).
// ---------------------------------------------------------------------------
__global__ void precompute_kernel(const float* __restrict__ Alog,
                                  const float* __restrict__ Bp,
                                  const float* __restrict__ Cp){
    const int h = blockIdx.x * blockDim.x + threadIdx.x;
    float am[NST], al2[NST], cs[NST];
    #pragma unroll
    for (int n = 0; n < NST; n++){
        const float A = -expf(Alog[h * NST + n]);
        al2[n] = A * LOG2E;
        am[n]  = exp2f(0.02f * al2[n]);
        cs[n]  = Cp[h * NST + n] * (am[n] - 1.f) * Bp[h * NST + n] / A;
    }
    #pragma unroll
    for (int i = 0; i < 8; i++){
        g_am2T[i * HDIM + h] = f2u(am[2 * i],  am[2 * i + 1]);
        g_al2T[i * HDIM + h] = f2u(al2[2 * i], al2[2 * i + 1]);
        g_c2T [i * HDIM + h] = f2u(cs[2 * i],  cs[2 * i + 1]);
    }
}

// ---------------------------------------------------------------------------
// TF32 tensor-core GEMM (unchanged): log_dt = U·Wᵀ + b; dt = clamp(exp()).
// Epilogue writes packed g_du[(b,l,h)] = {dt, u}.
// ---------------------------------------------------------------------------
__device__ __forceinline__ void cp16(float* s, const float* g){
    unsigned sa = (unsigned)__cvta_generic_to_shared(s);
    asm volatile("cp.async.cg.shared.global [%0], [%1], 16;" :: "r"(sa), "l"(g));
}
__device__ __forceinline__ void ldsm4(unsigned* r, unsigned addr){
    asm volatile("ldmatrix.sync.aligned.m8n8.x4.shared.b16 {%0,%1,%2,%3}, [%4];"
        : "=r"(r[0]), "=r"(r[1]), "=r"(r[2]), "=r"(r[3]) : "r"(addr));
}
__device__ __forceinline__ void mma_tf32(float* d, const unsigned* a,
                                         unsigned b0, unsigned b1){
    asm volatile(
        "mma.sync.aligned.m16n8k8.row.col.f32.tf32.tf32.f32 "
        "{%0,%1,%2,%3}, {%4,%5,%6,%7}, {%8,%9}, {%0,%1,%2,%3};"
        : "+f"(d[0]), "+f"(d[1]), "+f"(d[2]), "+f"(d[3])
        : "r"(a[0]), "r"(a[1]), "r"(a[2]), "r"(a[3]), "r"(b0), "r"(b1));
}

__global__ __launch_bounds__(256) void gemm_tf32_kernel(
        const float* __restrict__ U, const float* __restrict__ W,
        const float* __restrict__ bias){
    extern __shared__ float smem[];
    const int tid  = threadIdx.x;
    const int lane = tid & 31;
    const int wid  = tid >> 5;
    const int wm   = wid & 1;
    const int wn   = wid >> 1;
    const int bm   = blockIdx.y * 128;
    const int bn   = blockIdx.x * 128;

    float acc[4][4][4];
    #pragma unroll
    for (int i = 0; i < 4; i++)
        #pragma unroll
        for (int j = 0; j < 4; j++)
            #pragma unroll
            for (int r = 0; r < 4; r++) acc[i][j][r] = 0.f;

    const int lrow = tid >> 3;
    const int lkc  = tid & 7;

    unsigned smemBase = (unsigned)__cvta_generic_to_shared(smem);
    const unsigned aRowOff = (unsigned)((wm * 64 + (lane & 15)) * 128);
    const unsigned bRowOff = (unsigned)((wn * 32 + ((lane & 16) >> 1) + (lane & 7)) * 128);
    int physA[4], physB[4];
    #pragma unroll
    for (int ks = 0; ks < 4; ks++){
        physA[ks] = ((2 * ks + (lane >> 4)) ^ (lane & 7)) * 16;
        physB[ks] = ((2 * ks + ((lane >> 3) & 1)) ^ (lane & 7)) * 16;
    }

    #define LOAD_TILE(KT, STG) do {                                            \
        float* A_s = smem + (STG) * 8192;                                      \
        float* B_s = A_s + 4096;                                               \
        _Pragma("unroll")                                                      \
        for (int i = 0; i < 4; i++){                                           \
            int row  = lrow + i * 32;                                          \
            int phys = lkc ^ (row & 7);                                        \
            cp16(A_s + row * 32 + phys * 4,                                    \
                 U + (size_t)(bm + row) * 1024 + (KT) * 32 + lkc * 4);         \
            cp16(B_s + row * 32 + phys * 4,                                    \
                 W + (size_t)(bn + row) * 1024 + (KT) * 32 + lkc * 4);         \
        }                                                                      \
        asm volatile("cp.async.commit_group;");                                \
    } while (0)

    LOAD_TILE(0, 0);

    for (int kt = 0; kt < 32; kt++){
        const int cur = kt & 1;
        if (kt < 31) LOAD_TILE(kt + 1, cur ^ 1);
        if (kt < 31) asm volatile("cp.async.wait_group 1;");
        else         asm volatile("cp.async.wait_group 0;");
        __syncthreads();

        unsigned aB = smemBase + cur * 32768 + aRowOff;
        unsigned bB = smemBase + cur * 32768 + 16384 + bRowOff;
        #pragma unroll
        for (int ks = 0; ks < 4; ks++){
            unsigned a[4][4], bb[2][4];
            #pragma unroll
            for (int mt = 0; mt < 4; mt++)
                ldsm4(a[mt], aB + mt * 16 * 128 + physA[ks]);
            #pragma unroll
            for (int tp = 0; tp < 2; tp++)
                ldsm4(bb[tp], bB + tp * 16 * 128 + physB[ks]);
            #pragma unroll
            for (int mt = 0; mt < 4; mt++)
                #pragma unroll
                for (int nt = 0; nt < 4; nt++)
                    mma_tf32(acc[mt][nt], a[mt],
                             bb[nt >> 1][(nt & 1) * 2], bb[nt >> 1][(nt & 1) * 2 + 1]);
        }
        __syncthreads();
    }

    const int rbase = bm + wm * 64 + (lane >> 2);
    const int gbase = bn + wn * 32 + 2 * (lane & 3);
    float bv[4][2];
    #pragma unroll
    for (int nt = 0; nt < 4; nt++){
        bv[nt][0] = __ldg(bias + gbase + nt * 8);
        bv[nt][1] = __ldg(bias + gbase + nt * 8 + 1);
    }
    #pragma unroll
    for (int mt = 0; mt < 4; mt++)
        #pragma unroll
        for (int nt = 0; nt < 4; nt++)
            #pragma unroll
            for (int rr = 0; rr < 2; rr++){
                const int m = rbase + mt * 16 + rr * 8;
                const int g0 = gbase + nt * 8;
                float v0 = acc[mt][nt][rr * 2]     + bv[nt][0];
                float v1 = acc[mt][nt][rr * 2 + 1] + bv[nt][1];
                v0 = fminf(fmaxf(__expf(v0), DT_MIN_V), DT_MAX_V);
                v1 = fminf(fmaxf(__expf(v1), DT_MIN_V), DT_MAX_V);
                const float2 uv = *(const float2*)&U[(size_t)m * HDIM + g0];
                float4 w;
                w.x = v0; w.y = uv.x;
                w.z = v1; w.w = uv.y;
                *(float4*)&g_du[(size_t)m * HDIM + g0] = w;
            }
}

// ---------------------------------------------------------------------------
// Step macros (register-only, fully inline).
// ---------------------------------------------------------------------------
#define FAST_STEP(uu) do {                                                     \
    const u64 _u2 = f2u((uu), (uu));                                           \
    _Pragma("unroll")                                                          \
    for (int _i = 0; _i < 8; _i++) x2[_i] = ffma2(x2[_i], am2[_i], _u2);       \
} while (0)

#define SLOW_STEP(dtv, uv) do {                                                \
    _Pragma("unroll")                                                          \
    for (int _i = 0; _i < 8; _i++){                                            \
        float2 _xv = u2f(x2[_i]);                                              \
        const float2 _av = u2f(am2[_i]);                                       \
        const float2 _lv = u2f(al2[_i]);                                       \
        {                                                                      \
            const float _ab = exp2f((dtv) * _lv.x);                            \
            _xv.x = fmaf(_xv.x, _ab, (_ab - 1.f) / (_av.x - 1.f) * (uv));      \
        }                                                                      \
        {                                                                      \
            const float _ab = exp2f((dtv) * _lv.y);                            \
            _xv.y = fmaf(_xv.y, _ab, (_ab - 1.f) / (_av.y - 1.f) * (uv));      \
        }                                                                      \
        x2[_i] = f2u(_xv.x, _xv.y);                                            \
    }                                                                          \
} while (0)

// ---------------------------------------------------------------------------
// Pass 1: per-(channel,chunk) reduce. Tile register-resident (16x LDG.64).
// Constants from packed tables (8/16 coalesced LDG.64). P/S stores coalesced.
// ---------------------------------------------------------------------------
__global__ __launch_bounds__(128) void scan_reduce_kernel(){
    const int tid = threadIdx.x;
    const int s = blockIdx.x * 128 + tid;
    const int chunk = blockIdx.y;
    const int b = s >> 10;
    const int h = s & 1023;

    const size_t base = ((size_t)(b * LSEQ + chunk * CHLEN)) * HDIM + h;
    float2 d[CHLEN];
    #pragma unroll
    for (int j = 0; j < CHLEN; j++)
        d[j] = __ldg((const float2*)&g_du[base + (size_t)j * HDIM]);

    u64 am2[8], al2[8], x2[8];
    #pragma unroll
    for (int i = 0; i < 8; i++){
        am2[i] = g_am2T[i * HDIM + h];
        al2[i] = g_al2T[i * HDIM + h];
        x2[i] = 0ull;
    }

    float dtsum = 0.f;
    bool fast = true;
    #pragma unroll
    for (int j = 0; j < CHLEN; j++){ fast &= (d[j].x == DT_MAX_V); dtsum += d[j].x; }

    if (fast){
        #pragma unroll
        for (int j = 0; j < CHLEN; j++) FAST_STEP(d[j].y);
    } else {
        #pragma unroll
        for (int j = 0; j < CHLEN; j++){
            if (d[j].x == DT_MAX_V) FAST_STEP(d[j].y);
            else                    SLOW_STEP(d[j].x, d[j].y);
        }
    }

    // coalesced stores: layout [chunk][n][s]
    float* Pp = g_P + (size_t)chunk * NST * NCH + s;
    float* Sp = g_S + (size_t)chunk * NST * NCH + s;
    #pragma unroll
    for (int i = 0; i < 8; i++){
        const float2 lv = u2f(al2[i]);
        const float2 xv = u2f(x2[i]);
        Pp[(size_t)(2 * i)     * NCH] = exp2f(lv.x * dtsum);
        Pp[(size_t)(2 * i + 1) * NCH] = exp2f(lv.y * dtsum);
        Sp[(size_t)(2 * i)     * NCH] = xv.x;
        Sp[(size_t)(2 * i + 1) * NCH] = xv.y;
    }
}

// ---------------------------------------------------------------------------
// Pass 2: stitch 128-deep boundary chain. float4 over s (coalesced in new
// layout); 16 groups of (8 batched loads + 8 sequential folds).
// ---------------------------------------------------------------------------
__global__ void scan_stitch_kernel(){
    const int id = blockIdx.x * blockDim.x + threadIdx.x;  // 0..8191 = (n, s/4)
    const float4* P4 = (const float4*)g_P;
    const float4* S4 = (const float4*)g_S;
    float4* X4 = (float4*)g_Xin;
    const int stride = NST * NCH / 4;                      // 8192 float4/chunk
    float4 x = make_float4(0.f, 0.f, 0.f, 0.f);
    #pragma unroll 1
    for (int g = 0; g < NCHUNK / 8; g++){
        float4 Pg[8], Sg[8];
        #pragma unroll
        for (int c = 0; c < 8; c++){
            Pg[c] = P4[(size_t)(g * 8 + c) * stride + id];
            Sg[c] = S4[(size_t)(g * 8 + c) * stride + id];
        }
        #pragma unroll
        for (int c = 0; c < 8; c++){
            X4[(size_t)(g * 8 + c) * stride + id] = x;
            x.x = fmaf(Pg[c].x, x.x, Sg[c].x);
            x.y = fmaf(Pg[c].y, x.y, Sg[c].y);
            x.z = fmaf(Pg[c].z, x.z, Sg[c].z);
            x.w = fmaf(Pg[c].w, x.w, Sg[c].w);
        }
    }
}

// ---------------------------------------------------------------------------
// Pass 3: final scan + output. Constants from tables; Xin coalesced; al2
// loaded only when the slow path is needed.
// ---------------------------------------------------------------------------
__global__ __launch_bounds__(128) void scan_final_kernel(
        const float* __restrict__ Dp, float* __restrict__ out){
    const int tid = threadIdx.x;
    const int s = blockIdx.x * 128 + tid;
    const int chunk = blockIdx.y;
    const int b = s >> 10;
    const int h = s & 1023;

    const size_t base = ((size_t)(b * LSEQ + chunk * CHLEN)) * HDIM + h;
    float2 d[CHLEN];
    #pragma unroll
    for (int j = 0; j < CHLEN; j++)
        d[j] = __ldg((const float2*)&g_du[base + (size_t)j * HDIM]);

    u64 am2[8], c2[8], x2[8];
    #pragma unroll
    for (int i = 0; i < 8; i++){
        am2[i] = g_am2T[i * HDIM + h];
        c2[i]  = g_c2T [i * HDIM + h];
    }
    const float Dh = __ldg(Dp + h);

    {   // coalesced Xin loads: layout [chunk][n][s]
        const float* Xp = g_Xin + (size_t)chunk * NST * NCH + s;
        #pragma unroll
        for (int i = 0; i < 8; i++)
            x2[i] = f2u(Xp[(size_t)(2 * i) * NCH], Xp[(size_t)(2 * i + 1) * NCH]);
    }

    float* op = out + base;

    bool fast = true;
    #pragma unroll
    for (int j = 0; j < CHLEN; j++) fast &= (d[j].x == DT_MAX_V);

    #define Y_EMIT(j, uv) do {                                                 \
        u64 ya = 0ull, yb = 0ull;                                              \
        _Pragma("unroll")                                                      \
        for (int _i = 0; _i < 4; _i++) ya = ffma2(c2[_i], x2[_i], ya);         \
        _Pragma("unroll")                                                      \
        for (int _i = 4; _i < 8; _i++) yb = ffma2(c2[_i], x2[_i], yb);         \
        const float2 _va = u2f(ya);                                            \
        const float2 _vb = u2f(yb);                                            \
        op[(size_t)(j) * HDIM] = fmaf(Dh, (uv), (_va.x + _va.y) + (_vb.x + _vb.y)); \
    } while (0)

    if (fast){
        #pragma unroll
        for (int j = 0; j < CHLEN; j++){
            FAST_STEP(d[j].y);
            Y_EMIT(j, d[j].y);
        }
    } else {
        u64 al2[8];
        #pragma unroll
        for (int i = 0; i < 8; i++) al2[i] = g_al2T[i * HDIM + h];
        #pragma unroll
        for (int j = 0; j < CHLEN; j++){
            if (d[j].x == DT_MAX_V) FAST_STEP(d[j].y);
            else                    SLOW_STEP(d[j].x, d[j].y);
            Y_EMIT(j, d[j].y);
        }
    }
    #undef Y_EMIT
}

// ---------------------------------------------------------------------------
extern "C" void kernel_launch(void* const* d_in, const int* in_sizes, int n_in,
                              void* d_out, int out_size){
    const float* u    = (const float*)d_in[0];
    const float* Alog = (const float*)d_in[1];
    const float* Bp   = (const float*)d_in[2];
    const float* Cp   = (const float*)d_in[3];
    const float* Dp   = (const float*)d_in[4];
    const float* Wdt  = (const float*)d_in[5];
    const float* bdt  = (const float*)d_in[6];
    float* out = (float*)d_out;

    cudaFuncSetAttribute(gemm_tf32_kernel,
                         cudaFuncAttributeMaxDynamicSharedMemorySize, 65536);

    precompute_kernel<<<HDIM / 128, 128>>>(Alog, Bp, Cp);

    dim3 ggrid(HDIM / 128, MROWS / 128);            // (8, 32)
    gemm_tf32_kernel<<<ggrid, 256, 65536>>>(u, Wdt, bdt);

    scan_reduce_kernel<<<dim3(NCH / 128, NCHUNK), 128>>>();
    scan_stitch_kernel<<<NST * NCH / 4 / 256, 256>>>();
    scan_final_kernel<<<dim3(NCH / 128, NCHUNK), 128>>>(Dp, out);
}